// round 15
// baseline (speedup 1.0000x reference)
#include <cuda_runtime.h>
#include <cuda_fp16.h>
#include <cstdint>

// MaddnessConv2d, round 15: R10 inner loop + cp.async-hidden LUT setup.
// Pre-kernel converts LUT fp32->fp16 once into a __device__ global; the main
// kernel cp.async's the 32KB into smem and overlaps the copy with the
// gather+encode phase (LDG latency), waiting only before accumulation.
//
//   x:            (16, 64, 56, 56) f32
//   split_idxs:   (16, 4) i32
//   split_vals:   (16, 4, 8) f32
//   lookup_tables:(16, 16, 64) f32
//   bias:         (64,) f32
//   out:          (16, 64, 56, 56) f32
//
// out[p][ch] = sum_cb LUT[cb][e_cb(p)][ch] + bias[ch]. LUT rows (cb,e) are
// 128B fp16 (8 uint4 slots of 8 channels). 2 lanes/pixel: lane `part` reads
// slots s(rr) = ((2rr + 2(p&3))&7)|part -> every 8-lane LDS phase (4 px x
// 2 parts) covers all 8 bank-groups, independent of the code e. Two fp16
// trees (cb 0-7 / 8-15) merged in fp16; fp32 finalize + bias at the
// coalesced store via a packed-half2 pad-132 transpose in the dead LUT.

#define NCB   16
#define HW    3136          // 56*56
#define WID   56
#define TPB   256
#define NBLK  392           // 392*256 == 2*50176 exactly; 128 pixels/block

__device__ uint4 g_lut16[2048];   // row r = cb*16+e at [r*8 .. r*8+8)

__global__ void convert_lut_kernel(const float* __restrict__ lut) {
    const int i = blockIdx.x * blockDim.x + threadIdx.x;   // 0..2047
    const float4* l4 = (const float4*)lut;
    float4 a = l4[i * 2];
    float4 b = l4[i * 2 + 1];
    __half2 h0 = __floats2half2_rn(a.x, a.y);
    __half2 h1 = __floats2half2_rn(a.z, a.w);
    __half2 h2 = __floats2half2_rn(b.x, b.y);
    __half2 h3 = __floats2half2_rn(b.z, b.w);
    uint4 pk;
    pk.x = *(unsigned*)&h0;
    pk.y = *(unsigned*)&h1;
    pk.z = *(unsigned*)&h2;
    pk.w = *(unsigned*)&h3;
    g_lut16[i] = pk;
}

__global__ __launch_bounds__(TPB, 3) void maddness_conv2d_kernel(
    const float* __restrict__ x,
    const int*   __restrict__ split_idxs,
    const float* __restrict__ split_vals,
    const float* __restrict__ bias,
    float*       __restrict__ out)
{
    __shared__ uint4  s_lut[2048];        // 32KB; reused as transpose buffer
    __shared__ float  s_bias[64];
    __shared__ float  s_sval[16 * 33];    // stride-33 conflict-free walk
    __shared__ int    s_off[64];
    __shared__ int    s_kpos[64];

    const int tid = threadIdx.x;

    // --- kick off async LUT copy (32KB, 8 x 16B per thread), L2-broadcast ---
    {
        unsigned smem_a = (unsigned)__cvta_generic_to_shared(s_lut + tid);
        const uint4* src = g_lut16 + tid;
        #pragma unroll
        for (int j = 0; j < 8; j++) {
            asm volatile("cp.async.cg.shared.global [%0], [%1], 16;"
                         :: "r"(smem_a + j * (TPB * 16)),
                            "l"(src + j * TPB) : "memory");
        }
        asm volatile("cp.async.commit_group;" ::: "memory");
    }

    // --- small tables (overlapped with the async copy) ---
    if (tid < 64) {
        int cb = tid >> 2;                 // tid = cb*4 + t
        int si = split_idxs[tid];
        int f  = cb * 36 + si;
        int ch = f / 9;
        int r  = f - ch * 9;               // kernel position 0..8
        int dy = r / 3 - 1;
        int dx = r - (r / 3) * 3 - 1;
        s_off[tid]  = ch * HW + dy * WID + dx;
        s_kpos[tid] = r;
        s_bias[tid] = bias[tid];
    }
    #pragma unroll
    for (int i = tid; i < NCB * 32; i += TPB)
        s_sval[(i >> 5) * 33 + (i & 31)] = split_vals[i];
    __syncthreads();                       // small tables visible (LUT still in flight)

    // --- indices: 2 lanes per pixel ---
    const int gt   = blockIdx.x * TPB + tid;   // exact grid
    const int p    = gt >> 1;                  // pixel
    const int part = gt & 1;
    const int b    = p / HW;
    const int rem  = p - b * HW;
    const int y    = rem / WID;
    const int xw   = rem - y * WID;
    const float* xb = x + (size_t)b * 64 * HW + rem;

    // 3x3 validity bitmask (pad=1)
    unsigned vm = 0;
    #pragma unroll
    for (int ki = 0; ki < 3; ki++)
        #pragma unroll
        for (int kj = 0; kj < 3; kj++) {
            bool ok = ((unsigned)(y + ki - 1) < 56u) & ((unsigned)(xw + kj - 1) < 56u);
            vm |= (ok ? 1u : 0u) << (ki * 3 + kj);
        }

    // --- upfront gathers for my 8 codebooks (MLP=32); LUT copy in flight ---
    float v[32];
    #pragma unroll
    for (int c = 0; c < 8; c++)
        #pragma unroll
        for (int t = 0; t < 4; t++) {
            const int idx = (8 * part + c) * 4 + t;
            v[c * 4 + t] =
                ((vm >> s_kpos[idx]) & 1u) ? __ldg(xb + s_off[idx]) : 0.0f;
        }

    // --- threshold walk (conflict-free sval: bank = cb + 8t + e) ---
    unsigned mine = 0;
    #pragma unroll
    for (int c = 0; c < 8; c++) {
        const int cb = 8 * part + c;
        int e = 0;
        #pragma unroll
        for (int t = 0; t < 4; t++) {
            const float thr = s_sval[cb * 33 + t * 8 + e];
            e = 2 * e + (v[c * 4 + t] >= thr ? 1 : 0);
        }
        mine |= (unsigned)e << (4 * c);
    }

    // Merge: lane^1 is the other part of this pixel. One shuffle only.
    unsigned long long codes = (unsigned long long)mine << (32 * part);
    codes |= __shfl_xor_sync(0xffffffffu, codes, 1);

    // --- wait for the LUT copy, then accumulate (two fp16 trees) ---
    asm volatile("cp.async.wait_group 0;" ::: "memory");
    __syncthreads();

    const int rot2 = (p & 3) * 2;
    int soff[4];
    #pragma unroll
    for (int rr = 0; rr < 4; rr++)
        soff[rr] = ((2 * rr + rot2) & 7) | part;

    __half2 accA[4][4], accB[4][4];
    #pragma unroll
    for (int rr = 0; rr < 4; rr++)
        #pragma unroll
        for (int k = 0; k < 4; k++) {
            accA[rr][k] = __half2half2(__ushort_as_half(0));
            accB[rr][k] = __half2half2(__ushort_as_half(0));
        }

    #pragma unroll
    for (int cb = 0; cb < 8; cb++) {
        const int eA = (int)((codes >> (4 * cb)) & 15ull);
        const int eB = (int)((codes >> (4 * (cb + 8))) & 15ull);
        const uint4* rowA = s_lut + (cb * 16 + eA) * 8;
        const uint4* rowB = s_lut + ((cb + 8) * 16 + eB) * 8;
        #pragma unroll
        for (int rr = 0; rr < 4; rr++) {
            uint4 a  = rowA[soff[rr]];
            uint4 bq = rowB[soff[rr]];
            accA[rr][0] = __hadd2(accA[rr][0], *(__half2*)&a.x);
            accA[rr][1] = __hadd2(accA[rr][1], *(__half2*)&a.y);
            accA[rr][2] = __hadd2(accA[rr][2], *(__half2*)&a.z);
            accA[rr][3] = __hadd2(accA[rr][3], *(__half2*)&a.w);
            accB[rr][0] = __hadd2(accB[rr][0], *(__half2*)&bq.x);
            accB[rr][1] = __hadd2(accB[rr][1], *(__half2*)&bq.y);
            accB[rr][2] = __hadd2(accB[rr][2], *(__half2*)&bq.z);
            accB[rr][3] = __hadd2(accB[rr][3], *(__half2*)&bq.w);
        }
    }

    // --- fp16 tree merge + transpose via smem (reuse dead LUT region) ---
    __syncthreads();
    float4* s_buf = (float4*)s_lut;            // [g:8][px:132] packed half2
    const int pxl = tid >> 1;                  // local pixel 0..127
    #pragma unroll
    for (int rr = 0; rr < 4; rr++) {
        const int g = soff[rr];                // channel-8 group 0..7
        __half2 m0 = __hadd2(accA[rr][0], accB[rr][0]);
        __half2 m1 = __hadd2(accA[rr][1], accB[rr][1]);
        __half2 m2 = __hadd2(accA[rr][2], accB[rr][2]);
        __half2 m3 = __hadd2(accA[rr][3], accB[rr][3]);
        float4 pk;
        pk.x = *(float*)&m0;
        pk.y = *(float*)&m1;
        pk.z = *(float*)&m2;
        pk.w = *(float*)&m3;
        s_buf[g * 132 + pxl] = pk;
    }
    __syncthreads();

    // --- coalesced stores with fp32 finalize + bias ---
    // thread (q2 = tid>>7, pq = tid&127) stores groups q2*4 .. q2*4+3.
    const int q2 = tid >> 7;
    const int pq = tid & 127;
    const int pg = blockIdx.x * 128 + pq;      // global pixel
    const int bb = pg / HW;
    const int rr2 = pg - bb * HW;
    float* ob = out + (size_t)bb * 64 * HW + rr2;

    #pragma unroll
    for (int j = 0; j < 4; j++) {
        const int g = q2 * 4 + j;
        float4 pk = s_buf[g * 132 + pq];
        float2 f0 = __half22float2(*(__half2*)&pk.x);
        float2 f1 = __half22float2(*(__half2*)&pk.y);
        float2 f2 = __half22float2(*(__half2*)&pk.z);
        float2 f3 = __half22float2(*(__half2*)&pk.w);
        const int ch = 8 * g;
        ob[(ch + 0) * HW] = f0.x + s_bias[ch + 0];
        ob[(ch + 1) * HW] = f0.y + s_bias[ch + 1];
        ob[(ch + 2) * HW] = f1.x + s_bias[ch + 2];
        ob[(ch + 3) * HW] = f1.y + s_bias[ch + 3];
        ob[(ch + 4) * HW] = f2.x + s_bias[ch + 4];
        ob[(ch + 5) * HW] = f2.y + s_bias[ch + 5];
        ob[(ch + 6) * HW] = f3.x + s_bias[ch + 6];
        ob[(ch + 7) * HW] = f3.y + s_bias[ch + 7];
    }
}

extern "C" void kernel_launch(void* const* d_in, const int* in_sizes, int n_in,
                              void* d_out, int out_size)
{
    const float* x    = (const float*)d_in[0];
    const int*   sidx = (const int*)  d_in[1];
    const float* sval = (const float*)d_in[2];
    const float* lut  = (const float*)d_in[3];
    const float* bias = (const float*)d_in[4];
    float* out = (float*)d_out;

    convert_lut_kernel<<<8, 256>>>(lut);
    maddness_conv2d_kernel<<<NBLK, TPB>>>(x, sidx, sval, bias, out);
}

// round 16
// speedup vs baseline: 1.0108x; 1.0108x over previous
#include <cuda_runtime.h>
#include <cuda_fp16.h>
#include <cstdint>

// MaddnessConv2d, round 16: TPB=512, 4 lanes/pixel, 128 px/block, grid 392.
// Same one-wave grid and per-block setup as R10 (best ncu), but 16 warps per
// block -> ~42 resident warps/SM (2x R10) for latency hiding. Inner loop is
// R12's verified conflict-free scheme.
//
//   x:            (16, 64, 56, 56) f32
//   split_idxs:   (16, 4) i32
//   split_vals:   (16, 4, 8) f32
//   lookup_tables:(16, 16, 64) f32
//   bias:         (64,) f32
//   out:          (16, 64, 56, 56) f32
//
// out[p][ch] = sum_cb LUT[cb][e_cb(p)][ch] + bias[ch]. LUT rows (cb,e) are
// 128B fp16 (8 uint4 slots of 8 channels). Lane `part` in {0..3} of a pixel
// owns slots {2part, 2part+1}, visited in parity order (j + p) & 1 so each
// 8-lane LDS phase (2 px x 4 parts) covers all 8 banks regardless of the
// data-dependent code e. Two fp16 trees (cb 0-7 / 8-15) merged in fp16,
// fp32 finalize + bias at the coalesced store via pad-10 transpose overlay.

#define NCB   16
#define HW    3136          // 56*56
#define WID   56
#define TPB   512
#define NBLK  392           // 392*512 == 4*50176 exactly; 128 pixels/block

__global__ __launch_bounds__(TPB, 2) void maddness_conv2d_kernel(
    const float* __restrict__ x,
    const int*   __restrict__ split_idxs,
    const float* __restrict__ split_vals,
    const float* __restrict__ lut,
    const float* __restrict__ bias,
    float*       __restrict__ out)
{
    __shared__ uint4  s_lut[2048];        // 32KB; overlaid by transpose buffer
    __shared__ float  s_bias[64];
    __shared__ float  s_sval[16 * 33];    // stride-33 conflict-free walk
    __shared__ int    s_off[64];
    __shared__ int    s_kpos[64];

    const int tid = threadIdx.x;

    // --- per-block setup: convert LUT fp32 -> fp16 (128B rows), 8 iters ---
    {
        const float4* lut4 = (const float4*)lut;   // 4096 float4 (4 ch each)
        char* s_lutb = (char*)s_lut;
        #pragma unroll
        for (int i = tid; i < 4096; i += TPB) {
            float4 lv = lut4[i];
            __half2 h0 = __floats2half2_rn(lv.x, lv.y);
            __half2 h1 = __floats2half2_rn(lv.z, lv.w);
            uint2 pk;
            pk.x = *(unsigned*)&h0;
            pk.y = *(unsigned*)&h1;
            *(uint2*)(s_lutb + (i >> 4) * 128 + (i & 15) * 8) = pk;
        }
    }
    if (tid < 64) {
        int cb = tid >> 2;                 // tid = cb*4 + t
        int si = split_idxs[tid];
        int f  = cb * 36 + si;
        int ch = f / 9;
        int r  = f - ch * 9;               // kernel position 0..8
        int dy = r / 3 - 1;
        int dx = r - (r / 3) * 3 - 1;
        s_off[tid]  = ch * HW + dy * WID + dx;
        s_kpos[tid] = r;
        s_bias[tid] = bias[tid];
    }
    if (tid < NCB * 32)
        s_sval[(tid >> 5) * 33 + (tid & 31)] = split_vals[tid];
    __syncthreads();

    // --- indices: 4 lanes per pixel ---
    const int gt   = blockIdx.x * TPB + tid;   // exact grid
    const int p    = gt >> 2;                  // pixel
    const int part = gt & 3;                   // channel/codebook quarter
    const int b    = p / HW;
    const int rem  = p - b * HW;
    const int y    = rem / WID;
    const int xw   = rem - y * WID;
    const float* xb = x + (size_t)b * 64 * HW + rem;

    // 3x3 validity bitmask (pad=1)
    unsigned vm = 0;
    #pragma unroll
    for (int ki = 0; ki < 3; ki++)
        #pragma unroll
        for (int kj = 0; kj < 3; kj++) {
            bool ok = ((unsigned)(y + ki - 1) < 56u) & ((unsigned)(xw + kj - 1) < 56u);
            vm |= (ok ? 1u : 0u) << (ki * 3 + kj);
        }

    // --- upfront gathers for my 4 codebooks (MLP=16) ---
    float v[16];
    #pragma unroll
    for (int c = 0; c < 4; c++)
        #pragma unroll
        for (int t = 0; t < 4; t++) {
            const int idx = (4 * part + c) * 4 + t;
            v[c * 4 + t] =
                ((vm >> s_kpos[idx]) & 1u) ? __ldg(xb + s_off[idx]) : 0.0f;
        }

    // --- threshold walk ---
    unsigned mine = 0;
    #pragma unroll
    for (int c = 0; c < 4; c++) {
        const int cb = 4 * part + c;
        int e = 0;
        #pragma unroll
        for (int t = 0; t < 4; t++) {
            const float thr = s_sval[cb * 33 + t * 8 + e];
            e = 2 * e + (v[c * 4 + t] >= thr ? 1 : 0);
        }
        mine |= (unsigned)e << (4 * c);
    }

    // Merge codes across the 4 lanes of this pixel (lane bits 0-1 = part).
    unsigned long long codes = (unsigned long long)mine << (16 * part);
    codes |= __shfl_xor_sync(0xffffffffu, codes, 1);
    codes |= __shfl_xor_sync(0xffffffffu, codes, 2);

    // --- accumulate ch [16part, 16part+16), two fp16 trees ---
    // slot order: sl_j = 2part + ((j + p) & 1): 8-lane phase covers 8 banks.
    const int px1 = p & 1;
    const int sl0 = 2 * part + px1;
    const int sl1 = 2 * part + (px1 ^ 1);

    __half2 acc0A[4], acc0B[4], acc1A[4], acc1B[4];
    #pragma unroll
    for (int k = 0; k < 4; k++) {
        acc0A[k] = __half2half2(__ushort_as_half(0));
        acc0B[k] = __half2half2(__ushort_as_half(0));
        acc1A[k] = __half2half2(__ushort_as_half(0));
        acc1B[k] = __half2half2(__ushort_as_half(0));
    }

    #pragma unroll
    for (int cb = 0; cb < 8; cb++) {
        const int eA = (int)((codes >> (4 * cb)) & 15ull);
        const int eB = (int)((codes >> (4 * (cb + 8))) & 15ull);
        const uint4* rowA = s_lut + (cb * 16 + eA) * 8;
        const uint4* rowB = s_lut + ((cb + 8) * 16 + eB) * 8;
        uint4 a0 = rowA[sl0];
        uint4 b0 = rowB[sl0];
        uint4 a1 = rowA[sl1];
        uint4 b1 = rowB[sl1];
        acc0A[0] = __hadd2(acc0A[0], *(__half2*)&a0.x);
        acc0A[1] = __hadd2(acc0A[1], *(__half2*)&a0.y);
        acc0A[2] = __hadd2(acc0A[2], *(__half2*)&a0.z);
        acc0A[3] = __hadd2(acc0A[3], *(__half2*)&a0.w);
        acc0B[0] = __hadd2(acc0B[0], *(__half2*)&b0.x);
        acc0B[1] = __hadd2(acc0B[1], *(__half2*)&b0.y);
        acc0B[2] = __hadd2(acc0B[2], *(__half2*)&b0.z);
        acc0B[3] = __hadd2(acc0B[3], *(__half2*)&b0.w);
        acc1A[0] = __hadd2(acc1A[0], *(__half2*)&a1.x);
        acc1A[1] = __hadd2(acc1A[1], *(__half2*)&a1.y);
        acc1A[2] = __hadd2(acc1A[2], *(__half2*)&a1.z);
        acc1A[3] = __hadd2(acc1A[3], *(__half2*)&a1.w);
        acc1B[0] = __hadd2(acc1B[0], *(__half2*)&b1.x);
        acc1B[1] = __hadd2(acc1B[1], *(__half2*)&b1.y);
        acc1B[2] = __hadd2(acc1B[2], *(__half2*)&b1.z);
        acc1B[3] = __hadd2(acc1B[3], *(__half2*)&b1.w);
    }

    // --- fp16 merge + transpose into dead LUT region (pad-10) ---
    __syncthreads();                           // s_lut reads done block-wide
    uint4* s_buf = s_lut;                      // [px:128][g:8] at px*10 + g
    const int pxl = tid >> 2;                  // local pixel 0..127
    {
        __half2 m0 = __hadd2(acc0A[0], acc0B[0]);
        __half2 m1 = __hadd2(acc0A[1], acc0B[1]);
        __half2 m2 = __hadd2(acc0A[2], acc0B[2]);
        __half2 m3 = __hadd2(acc0A[3], acc0B[3]);
        uint4 pk;
        pk.x = *(unsigned*)&m0;
        pk.y = *(unsigned*)&m1;
        pk.z = *(unsigned*)&m2;
        pk.w = *(unsigned*)&m3;
        s_buf[pxl * 10 + sl0] = pk;            // group g == slot index
        m0 = __hadd2(acc1A[0], acc1B[0]);
        m1 = __hadd2(acc1A[1], acc1B[1]);
        m2 = __hadd2(acc1A[2], acc1B[2]);
        m3 = __hadd2(acc1A[3], acc1B[3]);
        pk.x = *(unsigned*)&m0;
        pk.y = *(unsigned*)&m1;
        pk.z = *(unsigned*)&m2;
        pk.w = *(unsigned*)&m3;
        s_buf[pxl * 10 + sl1] = pk;
    }
    __syncthreads();

    // --- coalesced stores with fp32 finalize + bias ---
    // thread (gq = tid>>7, px = tid&127) stores groups {2gq, 2gq+1}.
    const int gq = tid >> 7;                   // 0..3
    const int px = tid & 127;
    const int pg = blockIdx.x * 128 + px;      // global pixel
    const int bb = pg / HW;
    const int rr2 = pg - bb * HW;
    float* ob = out + (size_t)bb * 64 * HW + rr2;

    #pragma unroll
    for (int jj = 0; jj < 2; jj++) {
        const int g = 2 * gq + jj;
        uint4 pk = s_buf[px * 10 + g];
        float2 f0 = __half22float2(*(__half2*)&pk.x);
        float2 f1 = __half22float2(*(__half2*)&pk.y);
        float2 f2 = __half22float2(*(__half2*)&pk.z);
        float2 f3 = __half22float2(*(__half2*)&pk.w);
        const int ch = 8 * g;
        ob[(ch + 0) * HW] = f0.x + s_bias[ch + 0];
        ob[(ch + 1) * HW] = f0.y + s_bias[ch + 1];
        ob[(ch + 2) * HW] = f1.x + s_bias[ch + 2];
        ob[(ch + 3) * HW] = f1.y + s_bias[ch + 3];
        ob[(ch + 4) * HW] = f2.x + s_bias[ch + 4];
        ob[(ch + 5) * HW] = f2.y + s_bias[ch + 5];
        ob[(ch + 6) * HW] = f3.x + s_bias[ch + 6];
        ob[(ch + 7) * HW] = f3.y + s_bias[ch + 7];
    }
}

extern "C" void kernel_launch(void* const* d_in, const int* in_sizes, int n_in,
                              void* d_out, int out_size)
{
    const float* x    = (const float*)d_in[0];
    const int*   sidx = (const int*)  d_in[1];
    const float* sval = (const float*)d_in[2];
    const float* lut  = (const float*)d_in[3];
    const float* bias = (const float*)d_in[4];
    float* out = (float*)d_out;

    maddness_conv2d_kernel<<<NBLK, TPB>>>(x, sidx, sval, lut, bias, out);
}

// round 17
// speedup vs baseline: 1.0129x; 1.0022x over previous
#include <cuda_runtime.h>
#include <cuda_fp16.h>
#include <cstdint>

// MaddnessConv2d, round 17: R10 (best ncu) minus its serialization points.
// - separate transpose buffer (no LUT overlay) -> one fewer __syncthreads
// - batched LDS in the accumulate loop (8 loads before 32 HADD2)
// - cheaper 3x3 validity mask
// Shape unchanged: 392 blocks x 256 thr, 2 lanes/pixel, fp16 LUT in smem.
//
//   x:            (16, 64, 56, 56) f32
//   split_idxs:   (16, 4) i32
//   split_vals:   (16, 4, 8) f32
//   lookup_tables:(16, 16, 64) f32
//   bias:         (64,) f32
//   out:          (16, 64, 56, 56) f32
//
// out[p][ch] = sum_cb LUT[cb][e_cb(p)][ch] + bias[ch]. LUT rows (cb,e) are
// 128B fp16 (8 uint4 slots of 8 channels). Lane `part` reads slots
// s(rr) = ((2rr + 2(p&3))&7)|part -> every 8-lane LDS phase (4 px x 2 parts)
// covers all 8 bank-groups, independent of the data-dependent code e.
// Two fp16 trees (cb 0-7 / 8-15) merged in fp16; fp32 finalize + bias at
// the coalesced store via a packed-half2 pad-132 transpose.

#define NCB   16
#define HW    3136          // 56*56
#define WID   56
#define TPB   256
#define NBLK  392           // 392*256 == 2*50176 exactly; 128 pixels/block

__global__ __launch_bounds__(TPB, 3) void maddness_conv2d_kernel(
    const float* __restrict__ x,
    const int*   __restrict__ split_idxs,
    const float* __restrict__ split_vals,
    const float* __restrict__ lut,
    const float* __restrict__ bias,
    float*       __restrict__ out)
{
    __shared__ uint4  s_lut[2048];        // 32KB fp16 LUT (live whole kernel)
    __shared__ float4 s_buf[8 * 132];     // 16.9KB transpose buf [g:8][px:132]
    __shared__ float  s_bias[64];
    __shared__ float  s_sval[16 * 33];    // stride-33 conflict-free walk
    __shared__ int    s_off[64];
    __shared__ int    s_kpos[64];

    const int tid = threadIdx.x;

    // --- per-block setup: convert LUT fp32 -> fp16 (128B rows) ---
    {
        const float4* lut4 = (const float4*)lut;   // 4096 float4 (4 ch each)
        char* s_lutb = (char*)s_lut;
        #pragma unroll
        for (int i = tid; i < 4096; i += TPB) {
            float4 lv = lut4[i];
            __half2 h0 = __floats2half2_rn(lv.x, lv.y);
            __half2 h1 = __floats2half2_rn(lv.z, lv.w);
            uint2 pk;
            pk.x = *(unsigned*)&h0;
            pk.y = *(unsigned*)&h1;
            *(uint2*)(s_lutb + (i >> 4) * 128 + (i & 15) * 8) = pk;
        }
    }
    if (tid < 64) {
        int cb = tid >> 2;                 // tid = cb*4 + t
        int si = split_idxs[tid];
        int f  = cb * 36 + si;
        int ch = f / 9;
        int r  = f - ch * 9;               // kernel position 0..8
        int dy = r / 3 - 1;
        int dx = r - (r / 3) * 3 - 1;
        s_off[tid]  = ch * HW + dy * WID + dx;
        s_kpos[tid] = r;
        s_bias[tid] = bias[tid];
    }
    #pragma unroll
    for (int i = tid; i < NCB * 32; i += TPB)
        s_sval[(i >> 5) * 33 + (i & 31)] = split_vals[i];
    __syncthreads();

    // --- indices: 2 lanes per pixel ---
    const int gt   = blockIdx.x * TPB + tid;   // exact grid
    const int p    = gt >> 1;                  // pixel
    const int part = gt & 1;
    const int b    = p / HW;
    const int rem  = p - b * HW;
    const int y    = rem / WID;
    const int xw   = rem - y * WID;
    const float* xb = x + (size_t)b * 64 * HW + rem;

    // 3x3 validity bitmask (pad=1): vm bit (ki*3+kj)
    const unsigned rx = (unsigned)(xw > 0) | 2u | ((unsigned)(xw < 55) << 2);
    unsigned vm = rx << 3;                     // ki=1 always valid
    if (y > 0)  vm |= rx;
    if (y < 55) vm |= rx << 6;

    // --- upfront gathers for my 8 codebooks (MLP=32) ---
    float v[32];
    #pragma unroll
    for (int c = 0; c < 8; c++)
        #pragma unroll
        for (int t = 0; t < 4; t++) {
            const int idx = (8 * part + c) * 4 + t;
            v[c * 4 + t] =
                ((vm >> s_kpos[idx]) & 1u) ? __ldg(xb + s_off[idx]) : 0.0f;
        }

    // --- threshold walk (conflict-free sval: bank = cb + 8t + e) ---
    unsigned mine = 0;
    #pragma unroll
    for (int c = 0; c < 8; c++) {
        const int cb = 8 * part + c;
        int e = 0;
        #pragma unroll
        for (int t = 0; t < 4; t++) {
            const float thr = s_sval[cb * 33 + t * 8 + e];
            e = 2 * e + (v[c * 4 + t] >= thr ? 1 : 0);
        }
        mine |= (unsigned)e << (4 * c);
    }

    // Merge: lane^1 is the other part of this pixel. One shuffle only.
    unsigned long long codes = (unsigned long long)mine << (32 * part);
    codes |= __shfl_xor_sync(0xffffffffu, codes, 1);

    // --- accumulate, two fp16 trees (cb 0-7 / 8-15), batched loads ---
    const int rot2 = (p & 3) * 2;
    int soff[4];
    #pragma unroll
    for (int rr = 0; rr < 4; rr++)
        soff[rr] = ((2 * rr + rot2) & 7) | part;

    __half2 accA[4][4], accB[4][4];
    #pragma unroll
    for (int rr = 0; rr < 4; rr++)
        #pragma unroll
        for (int k = 0; k < 4; k++) {
            accA[rr][k] = __half2half2(__ushort_as_half(0));
            accB[rr][k] = __half2half2(__ushort_as_half(0));
        }

    #pragma unroll
    for (int cb = 0; cb < 8; cb++) {
        const int eA = (int)((codes >> (4 * cb)) & 15ull);
        const int eB = (int)((codes >> (4 * (cb + 8))) & 15ull);
        const uint4* rowA = s_lut + (cb * 16 + eA) * 8;
        const uint4* rowB = s_lut + ((cb + 8) * 16 + eB) * 8;
        // batch all 8 loads first (independent LDS, full MLP)
        uint4 a[4], bq[4];
        #pragma unroll
        for (int rr = 0; rr < 4; rr++) a[rr]  = rowA[soff[rr]];
        #pragma unroll
        for (int rr = 0; rr < 4; rr++) bq[rr] = rowB[soff[rr]];
        #pragma unroll
        for (int rr = 0; rr < 4; rr++) {
            accA[rr][0] = __hadd2(accA[rr][0], *(__half2*)&a[rr].x);
            accA[rr][1] = __hadd2(accA[rr][1], *(__half2*)&a[rr].y);
            accA[rr][2] = __hadd2(accA[rr][2], *(__half2*)&a[rr].z);
            accA[rr][3] = __hadd2(accA[rr][3], *(__half2*)&a[rr].w);
            accB[rr][0] = __hadd2(accB[rr][0], *(__half2*)&bq[rr].x);
            accB[rr][1] = __hadd2(accB[rr][1], *(__half2*)&bq[rr].y);
            accB[rr][2] = __hadd2(accB[rr][2], *(__half2*)&bq[rr].z);
            accB[rr][3] = __hadd2(accB[rr][3], *(__half2*)&bq[rr].w);
        }
    }

    // --- fp16 tree merge + transpose (separate buffer: no pre-barrier) ---
    const int pxl = tid >> 1;                  // local pixel 0..127
    #pragma unroll
    for (int rr = 0; rr < 4; rr++) {
        const int g = soff[rr];                // channel-8 group 0..7
        __half2 m0 = __hadd2(accA[rr][0], accB[rr][0]);
        __half2 m1 = __hadd2(accA[rr][1], accB[rr][1]);
        __half2 m2 = __hadd2(accA[rr][2], accB[rr][2]);
        __half2 m3 = __hadd2(accA[rr][3], accB[rr][3]);
        float4 pk;
        pk.x = *(float*)&m0;
        pk.y = *(float*)&m1;
        pk.z = *(float*)&m2;
        pk.w = *(float*)&m3;
        s_buf[g * 132 + pxl] = pk;
    }
    __syncthreads();

    // --- coalesced stores with fp32 finalize + bias ---
    // thread (q2 = tid>>7, pq = tid&127) stores groups q2*4 .. q2*4+3.
    const int q2 = tid >> 7;
    const int pq = tid & 127;
    const int pg = blockIdx.x * 128 + pq;      // global pixel
    const int bb = pg / HW;
    const int rr2 = pg - bb * HW;
    float* ob = out + (size_t)bb * 64 * HW + rr2;

    #pragma unroll
    for (int j = 0; j < 4; j++) {
        const int g = q2 * 4 + j;
        float4 pk = s_buf[g * 132 + pq];
        float2 f0 = __half22float2(*(__half2*)&pk.x);
        float2 f1 = __half22float2(*(__half2*)&pk.y);
        float2 f2 = __half22float2(*(__half2*)&pk.z);
        float2 f3 = __half22float2(*(__half2*)&pk.w);
        const int ch = 8 * g;
        ob[(ch + 0) * HW] = f0.x + s_bias[ch + 0];
        ob[(ch + 1) * HW] = f0.y + s_bias[ch + 1];
        ob[(ch + 2) * HW] = f1.x + s_bias[ch + 2];
        ob[(ch + 3) * HW] = f1.y + s_bias[ch + 3];
        ob[(ch + 4) * HW] = f2.x + s_bias[ch + 4];
        ob[(ch + 5) * HW] = f2.y + s_bias[ch + 5];
        ob[(ch + 6) * HW] = f3.x + s_bias[ch + 6];
        ob[(ch + 7) * HW] = f3.y + s_bias[ch + 7];
    }
}

extern "C" void kernel_launch(void* const* d_in, const int* in_sizes, int n_in,
                              void* d_out, int out_size)
{
    const float* x    = (const float*)d_in[0];
    const int*   sidx = (const int*)  d_in[1];
    const float* sval = (const float*)d_in[2];
    const float* lut  = (const float*)d_in[3];
    const float* bias = (const float*)d_in[4];
    float* out = (float*)d_out;

    maddness_conv2d_kernel<<<NBLK, TPB>>>(x, sidx, sval, lut, bias, out);
}